// round 4
// baseline (speedup 1.0000x reference)
#include <cuda_runtime.h>
#include <cstdint>
#include <cstddef>

// Problem constants (fixed by the benchmark shapes)
#define N_QUERY 32768   // 1024 rays * 32 samples
#define N_LIDAR 8192
#define FDIM    128
#define THREADS 512
#define QPB     256     // queries per block
#define SPLIT   4       // lidar quarters per block
#define CHUNK   (N_LIDAR / SPLIT)   // 2048 points per thread-task
#define NBLK    (N_QUERY / QPB)     // 128 blocks
#define TILE    64      // points per guarded best-update

using u64 = unsigned long long;

// ---- packed f32x2 helpers (sm_103a): bitwise-identical to scalar rn ops ----
__device__ __forceinline__ u64 dup2(float x) {
    u64 r; asm("mov.b64 %0, {%1, %1};" : "=l"(r) : "f"(x)); return r;
}
__device__ __forceinline__ u64 mul2(u64 a, u64 b) {
    u64 d; asm("mul.rn.f32x2 %0, %1, %2;" : "=l"(d) : "l"(a), "l"(b)); return d;
}
__device__ __forceinline__ u64 fma2(u64 a, u64 b, u64 c) {
    u64 d; asm("fma.rn.f32x2 %0, %1, %2, %3;" : "=l"(d) : "l"(a), "l"(b), "l"(c)); return d;
}
__device__ __forceinline__ u64 add2(u64 a, u64 b) {
    u64 d; asm("add.rn.f32x2 %0, %1, %2;" : "=l"(d) : "l"(a), "l"(b)); return d;
}
__device__ __forceinline__ float2 asf2(u64 v) {
    float2 f; asm("mov.b64 {%0, %1}, %2;" : "=f"(f.x), "=f"(f.y) : "l"(v)); return f;
}
__device__ __forceinline__ float min8(u64 a, u64 b, u64 c, u64 d) {
    float2 f0 = asf2(a), f1 = asf2(b), f2 = asf2(c), f3 = asf2(d);
    return fminf(fminf(fminf(f0.x, f0.y), fminf(f1.x, f1.y)),
                 fminf(fminf(f2.x, f2.y), fminf(f3.x, f3.y)));
}

// Exact first-index recovery in a 64-point tile (bit-identical scalar math).
__device__ __forceinline__ int recover_idx(
    const float* __restrict__ skx, const float* __restrict__ sky,
    const float* __restrict__ skz, const float* __restrict__ sks,
    int btile, float qx, float qy, float qz, float qs, float best)
{
    int bi = btile;
    bool found = false;
    #pragma unroll 4
    for (int i = 0; i < TILE; i++) {
        const int j = btile + i;
        float cross = __fmaf_rn(qz, skz[j],
                      __fmaf_rn(qy, sky[j], __fmul_rn(qx, skx[j])));
        float d2 = __fadd_rn(__fmaf_rn(cross, -2.0f, qs), sks[j]);
        if (!found && d2 == best) { bi = j; found = true; }
    }
    return bi;
}

__global__ void __launch_bounds__(THREADS, 1)
nn_gather_kernel(const float* __restrict__ pts,
                 const float* __restrict__ lidar,
                 const float* __restrict__ features,
                 float* __restrict__ out)
{
    extern __shared__ float sm[];
    float* skx = sm;
    float* sky = sm + N_LIDAR;
    float* skz = sm + 2 * N_LIDAR;
    float* sks = sm + 3 * N_LIDAR;
    float* cd2  = sm + 4 * N_LIDAR;                        // [SPLIT][QPB]
    int*   cidx = (int*)(sm + 4 * N_LIDAR + SPLIT * QPB);  // [SPLIT][QPB]
    int*   sidx = (int*)(sm + 4 * N_LIDAR + 2 * SPLIT * QPB); // [QPB]

    const int tid = threadIdx.x;

    // Cooperative SoA fill of lidar points + ||k||^2 (stepwise rounding (x^2+y^2)+z^2)
    for (int i = tid; i < N_LIDAR; i += THREADS) {
        float kx = lidar[3 * i + 0];
        float ky = lidar[3 * i + 1];
        float kz = lidar[3 * i + 2];
        skx[i] = kx; sky[i] = ky; skz[i] = kz;
        sks[i] = __fadd_rn(__fadd_rn(__fmul_rn(kx, kx), __fmul_rn(ky, ky)),
                           __fmul_rn(kz, kz));
    }
    __syncthreads();

    // Thread task: query pair (tid & 127) over lidar quarter (tid >> 7)
    const int pair = tid & 127;
    const int quarter = tid >> 7;
    const int q0 = 2 * pair;           // block-local query ids
    const int q1 = q0 + 1;
    const int m0 = blockIdx.x * QPB + q0;
    const int m1 = m0 + 1;

    const float qx0 = pts[3 * m0 + 0], qy0 = pts[3 * m0 + 1], qz0 = pts[3 * m0 + 2];
    const float qx1 = pts[3 * m1 + 0], qy1 = pts[3 * m1 + 1], qz1 = pts[3 * m1 + 2];
    const float qs0 = __fadd_rn(__fadd_rn(__fmul_rn(qx0, qx0), __fmul_rn(qy0, qy0)),
                                __fmul_rn(qz0, qz0));
    const float qs1 = __fadd_rn(__fadd_rn(__fmul_rn(qx1, qx1), __fmul_rn(qy1, qy1)),
                                __fmul_rn(qz1, qz1));

    const u64 QX0 = dup2(qx0), QY0 = dup2(qy0), QZ0 = dup2(qz0), QS0 = dup2(qs0);
    const u64 QX1 = dup2(qx1), QY1 = dup2(qy1), QZ1 = dup2(qz1), QS1 = dup2(qs1);
    const u64 NEG2 = dup2(-2.0f);

    float best0 = __int_as_float(0x7f800000), best1 = best0;
    int btile0 = quarter * CHUNK, btile1 = btile0;

    const int tbeg = quarter * CHUNK;
    const int tend = tbeg + CHUNK;

    for (int t = tbeg; t < tend; t += TILE) {
        float tm0 = __int_as_float(0x7f800000);
        float tm1 = tm0;

        #pragma unroll
        for (int g = 0; g < TILE / 8; g++) {
            const int j = t + 8 * g;

            // Component-streamed: only one component's 8 values live at a time.
            // cross = fma(qz,kz, fma(qy,ky, rn(qx*kx)))  — reference dot order
            ulonglong2 ka = *(const ulonglong2*)(skx + j);
            ulonglong2 kb = *(const ulonglong2*)(skx + j + 4);
            u64 c0a = mul2(QX0, ka.x), c0b = mul2(QX0, ka.y);
            u64 c0c = mul2(QX0, kb.x), c0d = mul2(QX0, kb.y);
            u64 c1a = mul2(QX1, ka.x), c1b = mul2(QX1, ka.y);
            u64 c1c = mul2(QX1, kb.x), c1d = mul2(QX1, kb.y);

            ka = *(const ulonglong2*)(sky + j);
            kb = *(const ulonglong2*)(sky + j + 4);
            c0a = fma2(QY0, ka.x, c0a); c0b = fma2(QY0, ka.y, c0b);
            c0c = fma2(QY0, kb.x, c0c); c0d = fma2(QY0, kb.y, c0d);
            c1a = fma2(QY1, ka.x, c1a); c1b = fma2(QY1, ka.y, c1b);
            c1c = fma2(QY1, kb.x, c1c); c1d = fma2(QY1, kb.y, c1d);

            ka = *(const ulonglong2*)(skz + j);
            kb = *(const ulonglong2*)(skz + j + 4);
            c0a = fma2(QZ0, ka.x, c0a); c0b = fma2(QZ0, ka.y, c0b);
            c0c = fma2(QZ0, kb.x, c0c); c0d = fma2(QZ0, kb.y, c0d);
            c1a = fma2(QZ1, ka.x, c1a); c1b = fma2(QZ1, ka.y, c1b);
            c1c = fma2(QZ1, kb.x, c1c); c1d = fma2(QZ1, kb.y, c1d);

            // d2 = rn( rn(qs - 2*cross) + ks )
            ka = *(const ulonglong2*)(sks + j);
            kb = *(const ulonglong2*)(sks + j + 4);
            c0a = add2(fma2(c0a, NEG2, QS0), ka.x);
            c0b = add2(fma2(c0b, NEG2, QS0), ka.y);
            c0c = add2(fma2(c0c, NEG2, QS0), kb.x);
            c0d = add2(fma2(c0d, NEG2, QS0), kb.y);
            c1a = add2(fma2(c1a, NEG2, QS1), ka.x);
            c1b = add2(fma2(c1b, NEG2, QS1), ka.y);
            c1c = add2(fma2(c1c, NEG2, QS1), kb.x);
            c1d = add2(fma2(c1d, NEG2, QS1), kb.y);

            tm0 = fminf(tm0, min8(c0a, c0b, c0c, c0d));
            tm1 = fminf(tm1, min8(c1a, c1b, c1c, c1d));
        }

        if (tm0 < best0) { best0 = tm0; btile0 = t; }  // strict < : earliest tile on ties
        if (tm1 < best1) { best1 = tm1; btile1 = t; }
    }

    // Exact first-index recovery within winning tiles (global lidar indices).
    const int bi0 = recover_idx(skx, sky, skz, sks, btile0, qx0, qy0, qz0, qs0, best0);
    const int bi1 = recover_idx(skx, sky, skz, sks, btile1, qx1, qy1, qz1, qs1, best1);

    cd2[quarter * QPB + q0] = best0;  cidx[quarter * QPB + q0] = bi0;
    cd2[quarter * QPB + q1] = best1;  cidx[quarter * QPB + q1] = bi1;
    __syncthreads();

    // Combine the 4 quarter-candidates per query (ascending quarter, strict <).
    if (tid < QPB) {
        float b = cd2[tid];
        int   i = cidx[tid];
        #pragma unroll
        for (int s = 1; s < SPLIT; s++) {
            float d = cd2[s * QPB + tid];
            int   j = cidx[s * QPB + tid];
            if (d < b) { b = d; i = j; }  // earlier quarter kept on ties (lower index)
        }
        sidx[tid] = i;
    }
    __syncthreads();

    // Warp-cooperative coalesced gather: one query row == 32 lanes x float4
    const int lane = tid & 31;
    const int warp = tid >> 5;
    const size_t qbase = (size_t)blockIdx.x * QPB;
    for (int q = warp; q < QPB; q += THREADS / 32) {
        const int src = sidx[q];
        const float4 v = *(const float4*)(features + (size_t)src * FDIM + lane * 4);
        *(float4*)(out + (qbase + q) * FDIM + lane * 4) = v;
    }
}

extern "C" void kernel_launch(void* const* d_in, const int* in_sizes, int n_in,
                              void* d_out, int out_size) {
    const float* pts      = (const float*)d_in[0];  // (1, 1024, 32, 3)
    const float* lidar    = (const float*)d_in[1];  // (1, 8192, 3)
    const float* features = (const float*)d_in[2];  // (1, 8192, 128)
    float* out = (float*)d_out;                     // (1, 1024, 32, 128)

    // 128 KB lidar SoA + combine scratch
    const int smem_bytes = (4 * N_LIDAR + 2 * SPLIT * QPB + QPB) * (int)sizeof(float);
    cudaFuncSetAttribute(nn_gather_kernel,
                         cudaFuncAttributeMaxDynamicSharedMemorySize, smem_bytes);

    nn_gather_kernel<<<NBLK, THREADS, smem_bytes>>>(pts, lidar, features, out);
}

// round 5
// speedup vs baseline: 1.0454x; 1.0454x over previous
#include <cuda_runtime.h>
#include <cstdint>
#include <cstddef>

// Problem constants (fixed by the benchmark shapes)
#define N_QUERY 32768   // 1024 rays * 32 samples
#define N_LIDAR 8192
#define FDIM    128
#define THREADS 256
#define QPB     256     // queries per block
#define SPLIT   4       // lidar quarters per block
#define Q       4       // queries per thread
#define CHUNK   (N_LIDAR / SPLIT)   // 2048 points per thread-task
#define NBLK    (N_QUERY / QPB)     // 128 blocks
#define TILE    64      // points per guarded best-update

using u64 = unsigned long long;

// ---- packed f32x2 helpers (sm_103a): bitwise-identical to scalar rn ops ----
__device__ __forceinline__ u64 dup2(float x) {
    u64 r; asm("mov.b64 %0, {%1, %1};" : "=l"(r) : "f"(x)); return r;
}
__device__ __forceinline__ u64 mul2(u64 a, u64 b) {
    u64 d; asm("mul.rn.f32x2 %0, %1, %2;" : "=l"(d) : "l"(a), "l"(b)); return d;
}
__device__ __forceinline__ u64 fma2(u64 a, u64 b, u64 c) {
    u64 d; asm("fma.rn.f32x2 %0, %1, %2, %3;" : "=l"(d) : "l"(a), "l"(b), "l"(c)); return d;
}
__device__ __forceinline__ u64 add2(u64 a, u64 b) {
    u64 d; asm("add.rn.f32x2 %0, %1, %2;" : "=l"(d) : "l"(a), "l"(b)); return d;
}
__device__ __forceinline__ float2 asf2(u64 v) {
    float2 f; asm("mov.b64 {%0, %1}, %2;" : "=f"(f.x), "=f"(f.y) : "l"(v)); return f;
}
__device__ __forceinline__ float min8(u64 a, u64 b, u64 c, u64 d) {
    float2 f0 = asf2(a), f1 = asf2(b), f2 = asf2(c), f3 = asf2(d);
    return fminf(fminf(fminf(f0.x, f0.y), fminf(f1.x, f1.y)),
                 fminf(fminf(f2.x, f2.y), fminf(f3.x, f3.y)));
}

// Exact first-index recovery in a 64-point tile (bit-identical scalar math).
__device__ __forceinline__ int recover_idx(
    const float* __restrict__ skx, const float* __restrict__ sky,
    const float* __restrict__ skz, const float* __restrict__ sks,
    int btile, float qx, float qy, float qz, float qs, float best)
{
    int bi = btile;
    bool found = false;
    #pragma unroll 4
    for (int i = 0; i < TILE; i++) {
        const int j = btile + i;
        float cross = __fmaf_rn(qz, skz[j],
                      __fmaf_rn(qy, sky[j], __fmul_rn(qx, skx[j])));
        float d2 = __fadd_rn(__fmaf_rn(cross, -2.0f, qs), sks[j]);
        if (!found && d2 == best) { bi = j; found = true; }
    }
    return bi;
}

__global__ void __launch_bounds__(THREADS, 1)
nn_gather_kernel(const float* __restrict__ pts,
                 const float* __restrict__ lidar,
                 const float* __restrict__ features,
                 float* __restrict__ out)
{
    extern __shared__ float sm[];
    float* skx = sm;
    float* sky = sm + N_LIDAR;
    float* skz = sm + 2 * N_LIDAR;
    float* sks = sm + 3 * N_LIDAR;
    float* cd2  = sm + 4 * N_LIDAR;                        // [SPLIT][QPB]
    int*   cidx = (int*)(sm + 4 * N_LIDAR + SPLIT * QPB);  // [SPLIT][QPB]
    int*   sidx = (int*)(sm + 4 * N_LIDAR + 2 * SPLIT * QPB); // [QPB]

    const int tid = threadIdx.x;

    // Cooperative SoA fill of lidar points + ||k||^2 (stepwise rounding (x^2+y^2)+z^2)
    for (int i = tid; i < N_LIDAR; i += THREADS) {
        float kx = lidar[3 * i + 0];
        float ky = lidar[3 * i + 1];
        float kz = lidar[3 * i + 2];
        skx[i] = kx; sky[i] = ky; skz[i] = kz;
        sks[i] = __fadd_rn(__fadd_rn(__fmul_rn(kx, kx), __fmul_rn(ky, ky)),
                           __fmul_rn(kz, kz));
    }
    __syncthreads();

    // Thread task: 4 consecutive queries (tid & 63) over lidar quarter (tid >> 6).
    // All 32 lanes of a warp share the same quarter -> all inner LDS are broadcasts.
    const int grp = tid & 63;
    const int quarter = tid >> 6;
    const int q0 = 4 * grp;                 // block-local query ids q0..q0+3
    const int m0 = blockIdx.x * QPB + q0;

    float qxs[Q], qys[Q], qzs[Q], qss[Q];
    u64 PQX[Q], PQY[Q], PQZ[Q], PQS[Q];
    #pragma unroll
    for (int q = 0; q < Q; q++) {
        qxs[q] = pts[3 * (m0 + q) + 0];
        qys[q] = pts[3 * (m0 + q) + 1];
        qzs[q] = pts[3 * (m0 + q) + 2];
        qss[q] = __fadd_rn(__fadd_rn(__fmul_rn(qxs[q], qxs[q]),
                                     __fmul_rn(qys[q], qys[q])),
                           __fmul_rn(qzs[q], qzs[q]));
        PQX[q] = dup2(qxs[q]); PQY[q] = dup2(qys[q]);
        PQZ[q] = dup2(qzs[q]); PQS[q] = dup2(qss[q]);
    }
    const u64 NEG2 = dup2(-2.0f);

    float best[Q];
    int btile[Q];
    #pragma unroll
    for (int q = 0; q < Q; q++) { best[q] = __int_as_float(0x7f800000); btile[q] = quarter * CHUNK; }

    const int tbeg = quarter * CHUNK;
    const int tend = tbeg + CHUNK;

    for (int t = tbeg; t < tend; t += TILE) {
        float tm[Q];
        #pragma unroll
        for (int q = 0; q < Q; q++) tm[q] = __int_as_float(0x7f800000);

        #pragma unroll
        for (int g = 0; g < TILE / 8; g++) {
            const int j = t + 8 * g;

            // cross = fma(qz,kz, fma(qy,ky, rn(qx*kx)))  — reference dot order
            ulonglong2 ka = *(const ulonglong2*)(skx + j);
            ulonglong2 kb = *(const ulonglong2*)(skx + j + 4);
            u64 acc[Q][4];
            #pragma unroll
            for (int q = 0; q < Q; q++) {
                acc[q][0] = mul2(PQX[q], ka.x); acc[q][1] = mul2(PQX[q], ka.y);
                acc[q][2] = mul2(PQX[q], kb.x); acc[q][3] = mul2(PQX[q], kb.y);
            }
            ka = *(const ulonglong2*)(sky + j);
            kb = *(const ulonglong2*)(sky + j + 4);
            #pragma unroll
            for (int q = 0; q < Q; q++) {
                acc[q][0] = fma2(PQY[q], ka.x, acc[q][0]);
                acc[q][1] = fma2(PQY[q], ka.y, acc[q][1]);
                acc[q][2] = fma2(PQY[q], kb.x, acc[q][2]);
                acc[q][3] = fma2(PQY[q], kb.y, acc[q][3]);
            }
            ka = *(const ulonglong2*)(skz + j);
            kb = *(const ulonglong2*)(skz + j + 4);
            #pragma unroll
            for (int q = 0; q < Q; q++) {
                acc[q][0] = fma2(PQZ[q], ka.x, acc[q][0]);
                acc[q][1] = fma2(PQZ[q], ka.y, acc[q][1]);
                acc[q][2] = fma2(PQZ[q], kb.x, acc[q][2]);
                acc[q][3] = fma2(PQZ[q], kb.y, acc[q][3]);
            }
            // d2 = rn( rn(qs - 2*cross) + ks )
            ka = *(const ulonglong2*)(sks + j);
            kb = *(const ulonglong2*)(sks + j + 4);
            #pragma unroll
            for (int q = 0; q < Q; q++) {
                acc[q][0] = add2(fma2(acc[q][0], NEG2, PQS[q]), ka.x);
                acc[q][1] = add2(fma2(acc[q][1], NEG2, PQS[q]), ka.y);
                acc[q][2] = add2(fma2(acc[q][2], NEG2, PQS[q]), kb.x);
                acc[q][3] = add2(fma2(acc[q][3], NEG2, PQS[q]), kb.y);
                tm[q] = fminf(tm[q], min8(acc[q][0], acc[q][1], acc[q][2], acc[q][3]));
            }
        }

        #pragma unroll
        for (int q = 0; q < Q; q++)
            if (tm[q] < best[q]) { best[q] = tm[q]; btile[q] = t; }  // strict < : earliest tile on ties
    }

    // Exact first-index recovery within winning tiles (global lidar indices),
    // then publish per-quarter candidates.
    #pragma unroll
    for (int q = 0; q < Q; q++) {
        const int bi = recover_idx(skx, sky, skz, sks, btile[q],
                                   qxs[q], qys[q], qzs[q], qss[q], best[q]);
        cd2[quarter * QPB + q0 + q]  = best[q];
        cidx[quarter * QPB + q0 + q] = bi;
    }
    __syncthreads();

    // Combine the 4 quarter-candidates per query (ascending quarter, strict <).
    if (tid < QPB) {
        float b = cd2[tid];
        int   i = cidx[tid];
        #pragma unroll
        for (int s = 1; s < SPLIT; s++) {
            float d = cd2[s * QPB + tid];
            int   j = cidx[s * QPB + tid];
            if (d < b) { b = d; i = j; }  // earlier quarter kept on ties (lower index)
        }
        sidx[tid] = i;
    }
    __syncthreads();

    // Warp-cooperative coalesced gather: one query row == 32 lanes x float4
    const int lane = tid & 31;
    const int warp = tid >> 5;
    const size_t qbase = (size_t)blockIdx.x * QPB;
    for (int qq = warp; qq < QPB; qq += THREADS / 32) {
        const int src = sidx[qq];
        const float4 v = *(const float4*)(features + (size_t)src * FDIM + lane * 4);
        *(float4*)(out + (qbase + qq) * FDIM + lane * 4) = v;
    }
}

extern "C" void kernel_launch(void* const* d_in, const int* in_sizes, int n_in,
                              void* d_out, int out_size) {
    const float* pts      = (const float*)d_in[0];  // (1, 1024, 32, 3)
    const float* lidar    = (const float*)d_in[1];  // (1, 8192, 3)
    const float* features = (const float*)d_in[2];  // (1, 8192, 128)
    float* out = (float*)d_out;                     // (1, 1024, 32, 128)

    // 128 KB lidar SoA + combine scratch
    const int smem_bytes = (4 * N_LIDAR + 2 * SPLIT * QPB + QPB) * (int)sizeof(float);
    cudaFuncSetAttribute(nn_gather_kernel,
                         cudaFuncAttributeMaxDynamicSharedMemorySize, smem_bytes);

    nn_gather_kernel<<<NBLK, THREADS, smem_bytes>>>(pts, lidar, features, out);
}

// round 6
// speedup vs baseline: 1.2036x; 1.1513x over previous
#include <cuda_runtime.h>
#include <cstdint>
#include <cstddef>

// Problem constants (fixed by the benchmark shapes)
#define N_QUERY 32768   // 1024 rays * 32 samples
#define N_LIDAR 8192
#define FDIM    128
#define THREADS 256
#define QPB     256     // queries per block
#define SPLIT   2       // lidar halves per block
#define Q       2       // queries per thread
#define CHUNK   (N_LIDAR / SPLIT)   // 4096 points per thread-task
#define NBLK    (N_QUERY / QPB)     // 128 blocks
#define TILE    64      // points per guarded best-update

using u64 = unsigned long long;

// ---- packed f32x2 helpers (sm_103a): bitwise-identical to scalar rn ops ----
__device__ __forceinline__ u64 dup2(float x) {
    u64 r; asm("mov.b64 %0, {%1, %1};" : "=l"(r) : "f"(x)); return r;
}
__device__ __forceinline__ u64 mul2(u64 a, u64 b) {
    u64 d; asm("mul.rn.f32x2 %0, %1, %2;" : "=l"(d) : "l"(a), "l"(b)); return d;
}
__device__ __forceinline__ u64 fma2(u64 a, u64 b, u64 c) {
    u64 d; asm("fma.rn.f32x2 %0, %1, %2, %3;" : "=l"(d) : "l"(a), "l"(b), "l"(c)); return d;
}
__device__ __forceinline__ u64 add2(u64 a, u64 b) {
    u64 d; asm("add.rn.f32x2 %0, %1, %2;" : "=l"(d) : "l"(a), "l"(b)); return d;
}
__device__ __forceinline__ float2 asf2(u64 v) {
    float2 f; asm("mov.b64 {%0, %1}, %2;" : "=f"(f.x), "=f"(f.y) : "l"(v)); return f;
}
__device__ __forceinline__ float min8(u64 a, u64 b, u64 c, u64 d) {
    float2 f0 = asf2(a), f1 = asf2(b), f2 = asf2(c), f3 = asf2(d);
    return fminf(fminf(fminf(f0.x, f0.y), fminf(f1.x, f1.y)),
                 fminf(fminf(f2.x, f2.y), fminf(f3.x, f3.y)));
}

// Exact first-index recovery in a 64-point tile (bit-identical scalar math).
__device__ __forceinline__ int recover_idx(
    const float* __restrict__ skx, const float* __restrict__ sky,
    const float* __restrict__ skz, const float* __restrict__ sks,
    int btile, float qx, float qy, float qz, float qs, float best)
{
    int bi = btile;
    bool found = false;
    #pragma unroll 4
    for (int i = 0; i < TILE; i++) {
        const int j = btile + i;
        float cross = __fmaf_rn(qz, skz[j],
                      __fmaf_rn(qy, sky[j], __fmul_rn(qx, skx[j])));
        float d2 = __fadd_rn(__fmaf_rn(cross, -2.0f, qs), sks[j]);
        if (!found && d2 == best) { bi = j; found = true; }
    }
    return bi;
}

__global__ void __launch_bounds__(THREADS, 1)
nn_gather_kernel(const float* __restrict__ pts,
                 const float* __restrict__ lidar,
                 const float* __restrict__ features,
                 float* __restrict__ out)
{
    extern __shared__ float sm[];
    float* skx = sm;
    float* sky = sm + N_LIDAR;
    float* skz = sm + 2 * N_LIDAR;
    float* sks = sm + 3 * N_LIDAR;
    float* cd2  = sm + 4 * N_LIDAR;                        // [SPLIT][QPB]
    int*   cidx = (int*)(sm + 4 * N_LIDAR + SPLIT * QPB);  // [SPLIT][QPB]
    int*   sidx = (int*)(sm + 4 * N_LIDAR + 2 * SPLIT * QPB); // [QPB]

    const int tid = threadIdx.x;

    // Cooperative SoA fill of lidar points + ||k||^2 (stepwise rounding (x^2+y^2)+z^2)
    for (int i = tid; i < N_LIDAR; i += THREADS) {
        float kx = lidar[3 * i + 0];
        float ky = lidar[3 * i + 1];
        float kz = lidar[3 * i + 2];
        skx[i] = kx; sky[i] = ky; skz[i] = kz;
        sks[i] = __fadd_rn(__fadd_rn(__fmul_rn(kx, kx), __fmul_rn(ky, ky)),
                           __fmul_rn(kz, kz));
    }
    __syncthreads();

    // Thread task: query pair (tid & 127) over lidar half (tid >> 7).
    // All 32 lanes of a warp share the same half -> all inner LDS are broadcasts.
    const int pair = tid & 127;
    const int half = tid >> 7;
    const int q0 = 2 * pair;                // block-local query ids q0, q0+1
    const int m0 = blockIdx.x * QPB + q0;

    const float qx0 = pts[3 * m0 + 0], qy0 = pts[3 * m0 + 1], qz0 = pts[3 * m0 + 2];
    const float qx1 = pts[3 * m0 + 3], qy1 = pts[3 * m0 + 4], qz1 = pts[3 * m0 + 5];
    const float qs0 = __fadd_rn(__fadd_rn(__fmul_rn(qx0, qx0), __fmul_rn(qy0, qy0)),
                                __fmul_rn(qz0, qz0));
    const float qs1 = __fadd_rn(__fadd_rn(__fmul_rn(qx1, qx1), __fmul_rn(qy1, qy1)),
                                __fmul_rn(qz1, qz1));

    const u64 QX0 = dup2(qx0), QY0 = dup2(qy0), QZ0 = dup2(qz0), QS0 = dup2(qs0);
    const u64 QX1 = dup2(qx1), QY1 = dup2(qy1), QZ1 = dup2(qz1), QS1 = dup2(qs1);
    const u64 NEG2 = dup2(-2.0f);

    float best0 = __int_as_float(0x7f800000), best1 = best0;
    int btile0 = half * CHUNK, btile1 = btile0;

    const int tbeg = half * CHUNK;
    const int tend = tbeg + CHUNK;

    for (int t = tbeg; t < tend; t += TILE) {
        float tm0 = __int_as_float(0x7f800000);
        float tm1 = tm0;

        #pragma unroll
        for (int g = 0; g < TILE / 8; g++) {
            const int j = t + 8 * g;

            // cross = fma(qz,kz, fma(qy,ky, rn(qx*kx)))  — reference dot order
            ulonglong2 ka = *(const ulonglong2*)(skx + j);
            ulonglong2 kb = *(const ulonglong2*)(skx + j + 4);
            u64 a0 = mul2(QX0, ka.x), a1 = mul2(QX0, ka.y);
            u64 a2 = mul2(QX0, kb.x), a3 = mul2(QX0, kb.y);
            u64 b0 = mul2(QX1, ka.x), b1 = mul2(QX1, ka.y);
            u64 b2 = mul2(QX1, kb.x), b3 = mul2(QX1, kb.y);

            ka = *(const ulonglong2*)(sky + j);
            kb = *(const ulonglong2*)(sky + j + 4);
            a0 = fma2(QY0, ka.x, a0); a1 = fma2(QY0, ka.y, a1);
            a2 = fma2(QY0, kb.x, a2); a3 = fma2(QY0, kb.y, a3);
            b0 = fma2(QY1, ka.x, b0); b1 = fma2(QY1, ka.y, b1);
            b2 = fma2(QY1, kb.x, b2); b3 = fma2(QY1, kb.y, b3);

            ka = *(const ulonglong2*)(skz + j);
            kb = *(const ulonglong2*)(skz + j + 4);
            a0 = fma2(QZ0, ka.x, a0); a1 = fma2(QZ0, ka.y, a1);
            a2 = fma2(QZ0, kb.x, a2); a3 = fma2(QZ0, kb.y, a3);
            b0 = fma2(QZ1, ka.x, b0); b1 = fma2(QZ1, ka.y, b1);
            b2 = fma2(QZ1, kb.x, b2); b3 = fma2(QZ1, kb.y, b3);

            // d2 = rn( rn(qs - 2*cross) + ks )
            ka = *(const ulonglong2*)(sks + j);
            kb = *(const ulonglong2*)(sks + j + 4);
            a0 = add2(fma2(a0, NEG2, QS0), ka.x);
            a1 = add2(fma2(a1, NEG2, QS0), ka.y);
            a2 = add2(fma2(a2, NEG2, QS0), kb.x);
            a3 = add2(fma2(a3, NEG2, QS0), kb.y);
            b0 = add2(fma2(b0, NEG2, QS1), ka.x);
            b1 = add2(fma2(b1, NEG2, QS1), ka.y);
            b2 = add2(fma2(b2, NEG2, QS1), kb.x);
            b3 = add2(fma2(b3, NEG2, QS1), kb.y);

            tm0 = fminf(tm0, min8(a0, a1, a2, a3));
            tm1 = fminf(tm1, min8(b0, b1, b2, b3));
        }

        if (tm0 < best0) { best0 = tm0; btile0 = t; }  // strict < : earliest tile on ties
        if (tm1 < best1) { best1 = tm1; btile1 = t; }
    }

    // Exact first-index recovery within winning tiles (global lidar indices).
    const int bi0 = recover_idx(skx, sky, skz, sks, btile0, qx0, qy0, qz0, qs0, best0);
    const int bi1 = recover_idx(skx, sky, skz, sks, btile1, qx1, qy1, qz1, qs1, best1);

    cd2[half * QPB + q0]     = best0;  cidx[half * QPB + q0]     = bi0;
    cd2[half * QPB + q0 + 1] = best1;  cidx[half * QPB + q0 + 1] = bi1;
    __syncthreads();

    // Combine the 2 half-candidates per query (ascending half, strict <).
    if (tid < QPB) {
        float b = cd2[tid];
        int   i = cidx[tid];
        float d = cd2[QPB + tid];
        int   j = cidx[QPB + tid];
        if (d < b) { b = d; i = j; }  // earlier half kept on ties (lower index)
        sidx[tid] = i;
    }
    __syncthreads();

    // Warp-cooperative coalesced gather: one query row == 32 lanes x float4
    const int lane = tid & 31;
    const int warp = tid >> 5;
    const size_t qbase = (size_t)blockIdx.x * QPB;
    for (int qq = warp; qq < QPB; qq += THREADS / 32) {
        const int src = sidx[qq];
        const float4 v = *(const float4*)(features + (size_t)src * FDIM + lane * 4);
        *(float4*)(out + (qbase + qq) * FDIM + lane * 4) = v;
    }
}

extern "C" void kernel_launch(void* const* d_in, const int* in_sizes, int n_in,
                              void* d_out, int out_size) {
    const float* pts      = (const float*)d_in[0];  // (1, 1024, 32, 3)
    const float* lidar    = (const float*)d_in[1];  // (1, 8192, 3)
    const float* features = (const float*)d_in[2];  // (1, 8192, 128)
    float* out = (float*)d_out;                     // (1, 1024, 32, 128)

    // 128 KB lidar SoA + combine scratch
    const int smem_bytes = (4 * N_LIDAR + 2 * SPLIT * QPB + QPB) * (int)sizeof(float);
    cudaFuncSetAttribute(nn_gather_kernel,
                         cudaFuncAttributeMaxDynamicSharedMemorySize, smem_bytes);

    nn_gather_kernel<<<NBLK, THREADS, smem_bytes>>>(pts, lidar, features, out);
}